// round 14
// baseline (speedup 1.0000x reference)
#include <cuda_runtime.h>
#include <cuda_fp16.h>
#include <math.h>

#define NN 50000
#define EE 800000

// ---------------- scratch (static device globals; no allocations) ----------------
__device__ float  g_dinv[NN];
__device__ int    g_deg[NN];
__device__ int    g_rowptr[NN + 1];
__device__ int    g_bsum[256];
__device__ int    g_esrc[EE];
__device__ float  g_ew[EE];
__device__ float  g_h  [(size_t)NN * 64];        // inter-layer activations (fp32)
__device__ __half g_hh [(size_t)NN * 64];        // fp16 mirror of h
__device__ __half g_b3h[(size_t)2 * NN * 64];    // fp16 out0 / out_t0 (gather source)
__device__ float  g_agg[(size_t)2 * NN * 64];    // prop destination (pc / p2)
__device__ float  g_b2 [(size_t)2 * NN * 64];    // final per-k
__device__ float  g_w2all[16384 + 4 * 8192];     // folded W2 for layers 1-5

// ---------------- setup kernels ----------------
__global__ void k_zero_int(int* p, int n) {
    int i = blockIdx.x * blockDim.x + threadIdx.x;
    if (i < n) p[i] = 0;
}
__global__ void k_deg(const int* __restrict__ col, int* __restrict__ deg, int E) {
    int e = blockIdx.x * blockDim.x + threadIdx.x;
    if (e < E) atomicAdd(&deg[col[e]], 1);
}
__global__ void k_dinv(const int* __restrict__ deg, float* __restrict__ dinv, int n) {
    int i = blockIdx.x * blockDim.x + threadIdx.x;
    if (i < n) {
        int d = deg[i];
        dinv[i] = (d > 0) ? rsqrtf((float)d) : 0.f;
    }
}
__global__ void k_blocksum(const int* __restrict__ deg, int* __restrict__ bsum, int n) {
    __shared__ int s[256];
    int i = blockIdx.x * 256 + threadIdx.x;
    s[threadIdx.x] = (i < n) ? deg[i] : 0;
    __syncthreads();
    for (int o = 128; o > 0; o >>= 1) {
        if (threadIdx.x < o) s[threadIdx.x] += s[threadIdx.x + o];
        __syncthreads();
    }
    if (threadIdx.x == 0) bsum[blockIdx.x] = s[0];
}
__global__ void k_scanb(int* bsum, int nb) {
    __shared__ int s[256];
    int v = (threadIdx.x < nb) ? bsum[threadIdx.x] : 0;
    s[threadIdx.x] = v;
    __syncthreads();
    for (int o = 1; o < 256; o <<= 1) {
        int t = (threadIdx.x >= o) ? s[threadIdx.x - o] : 0;
        __syncthreads();
        s[threadIdx.x] += t;
        __syncthreads();
    }
    if (threadIdx.x < nb) bsum[threadIdx.x] = s[threadIdx.x] - v;
}
__global__ void k_scanfinal(const int* __restrict__ deg, const int* __restrict__ bsum,
                            int* __restrict__ rowptr, int n, int E) {
    __shared__ int s[256];
    int i = blockIdx.x * 256 + threadIdx.x;
    int v = (i < n) ? deg[i] : 0;
    s[threadIdx.x] = v;
    __syncthreads();
    for (int o = 1; o < 256; o <<= 1) {
        int t = (threadIdx.x >= o) ? s[threadIdx.x - o] : 0;
        __syncthreads();
        s[threadIdx.x] += t;
        __syncthreads();
    }
    if (i < n) rowptr[i] = bsum[blockIdx.x] + s[threadIdx.x] - v;
    if (i == 0 && blockIdx.x == 0) rowptr[n] = E;
}
__global__ void k_fill(const int* __restrict__ row, const int* __restrict__ col,
                       const float* __restrict__ dinv,
                       const int* __restrict__ rowptr, int* __restrict__ counter,
                       int* __restrict__ esrc, float* __restrict__ ew, int E) {
    int e = blockIdx.x * blockDim.x + threadIdx.x;
    if (e >= E) return;
    int r = row[e], t = col[e];
    int p = rowptr[t] + atomicAdd(&counter[t], 1);
    esrc[p] = r;
    ew[p] = dinv[r] * dinv[t];
}

// ---------------- batched weight fold: W2_k = rw1_k + 0.6*(0.5*(iw0+iw1))@dw1_k ----------------
struct FoldArgs {
    const float* iw[5];
    const float* rw1[5];
    const float* dw1[5];
    float* w2[5];
    int fi[5];
};
__global__ void k_fold_all(FoldArgs a) {
    int l = blockIdx.x >> 1, k = blockIdx.x & 1;
    int fi = a.fi[l];
    __shared__ float dws[64 * 64];
    const float* dwk = a.dw1[l] + k * 64 * 64;
    for (int i = threadIdx.x; i < 64 * 64; i += blockDim.x) dws[i] = dwk[i];
    __syncthreads();
    const float* iw = a.iw[l];
    const float* rwk = a.rw1[l] + (long)k * fi * 64;
    float* w2k = a.w2[l] + (long)k * fi * 64;
    for (int idx = threadIdx.x; idx < fi * 64; idx += blockDim.x) {
        int f = idx >> 6, q = idx & 63;
        float s = 0.f;
#pragma unroll 8
        for (int o = 0; o < 64; o++) {
            float miw = 0.5f * (iw[f * 64 + o] + iw[(long)fi * 64 + f * 64 + o]);
            s += miw * dws[o * 64 + q];
        }
        w2k[idx] = rwk[idx] + 0.6f * s;
    }
}

// ---------------- message passing: CSR gather, fp16 source, 4x unrolled (MLP=4) ----------------
template<int CH, int F8K>
__global__ void k_prop_h(const __half* __restrict__ src, float* __restrict__ dst,
                         const int* __restrict__ rowptr, const int* __restrict__ esrc,
                         const float* __restrict__ ew, int N, long sKh, long sKf) {
    int idx = blockIdx.x * blockDim.x + threadIdx.x;
    int n = idx / CH;
    if (n >= N) return;
    int c = idx - n * CH;
    int k = c / F8K;
    int cc = c - k * F8K;
    const int F = F8K * 8;
    const __half* sb = src + (long)k * sKh + cc * 8;
    float acc[8];
#pragma unroll
    for (int q = 0; q < 8; q++) acc[q] = 0.f;
    int s0 = rowptr[n], s1 = rowptr[n + 1];

    int j = s0;
    for (; j + 4 <= s1; j += 4) {
        // batch the index/weight loads, then 4 independent 128B gathers (MLP=4)
        int i0 = esrc[j], i1 = esrc[j + 1], i2 = esrc[j + 2], i3 = esrc[j + 3];
        float w0 = ew[j], w1 = ew[j + 1], w2 = ew[j + 2], w3 = ew[j + 3];
        uint4 u0 = *(const uint4*)(sb + (long)i0 * F);
        uint4 u1 = *(const uint4*)(sb + (long)i1 * F);
        uint4 u2 = *(const uint4*)(sb + (long)i2 * F);
        uint4 u3 = *(const uint4*)(sb + (long)i3 * F);
        const __half2* h0 = (const __half2*)&u0;
        const __half2* h1 = (const __half2*)&u1;
        const __half2* h2 = (const __half2*)&u2;
        const __half2* h3 = (const __half2*)&u3;
#pragma unroll
        for (int q = 0; q < 4; q++) {
            float2 f0 = __half22float2(h0[q]);
            float2 f1 = __half22float2(h1[q]);
            float2 f2 = __half22float2(h2[q]);
            float2 f3 = __half22float2(h3[q]);
            acc[2 * q]     += f0.x * w0 + f1.x * w1 + f2.x * w2 + f3.x * w3;
            acc[2 * q + 1] += f0.y * w0 + f1.y * w1 + f2.y * w2 + f3.y * w3;
        }
    }
    for (; j < s1; j++) {
        int s = esrc[j];
        float wv = ew[j];
        uint4 u = *(const uint4*)(sb + (long)s * F);
        const __half2* hp = (const __half2*)&u;
#pragma unroll
        for (int q = 0; q < 4; q++) {
            float2 f = __half22float2(hp[q]);
            acc[2 * q]     += f.x * wv;
            acc[2 * q + 1] += f.y * wv;
        }
    }
    float* db = dst + (long)k * sKf + ((long)n * F + cc * 8);
    *(float4*)db       = make_float4(acc[0], acc[1], acc[2], acc[3]);
    *(float4*)(db + 4) = make_float4(acc[4], acc[5], acc[6], acc[7]);
}

// ---------------- tf32 tensor-core helpers ----------------
__device__ __forceinline__ float to_tf32(float x) {
    unsigned u;
    asm("cvt.rna.tf32.f32 %0, %1;" : "=r"(u) : "f"(x));
    return __uint_as_float(u);
}
__device__ __forceinline__ void mma_tf32(float* c, float a0, float a1, float a2, float a3,
                                         float b0, float b1) {
    asm volatile(
        "mma.sync.aligned.m16n8k8.row.col.f32.tf32.tf32.f32 "
        "{%0,%1,%2,%3}, {%4,%5,%6,%7}, {%8,%9}, {%0,%1,%2,%3};\n"
        : "+f"(c[0]), "+f"(c[1]), "+f"(c[2]), "+f"(c[3])
        : "r"(__float_as_uint(a0)), "r"(__float_as_uint(a1)),
          "r"(__float_as_uint(a2)), "r"(__float_as_uint(a3)),
          "r"(__float_as_uint(b0)), "r"(__float_as_uint(b1)));
}

// ---------------- fused GEMM via tf32 mma.sync (per-k via blockIdx.z) ----------------
// C[k] = act( [A1|A2][k] @ [B1;B2][k] + D1[k] + bias_scalar )
template<int FO>
__global__ __launch_bounds__(256)
void k_gemm_tc(const float* __restrict__ A1, long a1K, int fin1, int lda1,
               const float* __restrict__ A2, long a2K, int lda2,
               const float* __restrict__ B1, long b1K,
               const float* __restrict__ B2, long b2K,
               int Fin,
               const float* __restrict__ D1, long dK,
               const float* __restrict__ bias,
               float* __restrict__ Cf, __half* __restrict__ Ch, long cK, long chK,
               int nRows, int act) {
    constexpr int NT = FO / 8;
    __shared__ float As[128][36];
    __shared__ float Bf[4 * NT * 32 * 2];

    const int k = blockIdx.z;
    const float* a1p = A1 + (long)k * a1K;
    const float* a2p = A2 ? (A2 + (long)k * a2K) : nullptr;
    const float* b1p = B1 + (long)k * b1K;
    const float* b2p = B2 ? (B2 + (long)k * b2K) : nullptr;
    const float* d1 = D1 ? (D1 + (long)k * dK) : nullptr;
    float* cf = Cf ? (Cf + (long)k * cK) : nullptr;
    __half* ch = Ch ? (Ch + (long)k * chK) : nullptr;

    const int tid = threadIdx.x;
    const int lane = tid & 31;
    const int warp = tid >> 5;
    const int g  = lane >> 2;
    const int tg = lane & 3;
    const int row0 = blockIdx.x * 128;
    const int wr = warp * 16;

    float acc[NT][4];
#pragma unroll
    for (int nt = 0; nt < NT; nt++)
#pragma unroll
        for (int q = 0; q < 4; q++) acc[nt][q] = 0.f;

    for (int kc = 0; kc < Fin; kc += 32) {
        __syncthreads();
        const float* Asrc; int lda, coff;
        if (kc < fin1) { Asrc = a1p; lda = lda1; coff = kc; }
        else           { Asrc = a2p; lda = lda2; coff = kc - fin1; }
        for (int i = tid; i < 128 * 8; i += 256) {
            int r = i >> 3, c4 = (i & 7) * 4;
            int gr = row0 + r;
            float4 v = make_float4(0.f, 0.f, 0.f, 0.f);
            if (gr < nRows) v = *(const float4*)(Asrc + (long)gr * lda + coff + c4);
            v.x = to_tf32(v.x); v.y = to_tf32(v.y); v.z = to_tf32(v.z); v.w = to_tf32(v.w);
            *(float4*)&As[r][c4] = v;
        }
        for (int i = tid; i < 4 * NT * 64; i += 256) {
            int r2 = i & 1;
            int lane2 = (i >> 1) & 31;
            int nt = (i >> 6) % NT;
            int ks = i / (64 * NT);
            int tg2 = lane2 & 3, g2 = lane2 >> 2;
            int kl = ks * 8 + tg2 + r2 * 4;
            int n  = nt * 8 + g2;
            int kg = kc + kl;
            float bv = (kg < fin1) ? b1p[kg * FO + n] : b2p[(kg - fin1) * FO + n];
            Bf[i] = to_tf32(bv);
        }
        __syncthreads();
#pragma unroll
        for (int ks = 0; ks < 4; ks++) {
            float a0 = As[wr + g][ks * 8 + tg];
            float a1 = As[wr + g + 8][ks * 8 + tg];
            float a2 = As[wr + g][ks * 8 + tg + 4];
            float a3 = As[wr + g + 8][ks * 8 + tg + 4];
#pragma unroll
            for (int nt = 0; nt < NT; nt++) {
                float2 b = *(const float2*)&Bf[((ks * NT + nt) * 32 + lane) * 2];
                mma_tf32(acc[nt], a0, a1, a2, a3, b.x, b.y);
            }
        }
    }

    float bvs = bias ? __ldg(bias) : 0.f;
    int r0 = row0 + wr + g;
    int r1 = r0 + 8;
#pragma unroll
    for (int nt = 0; nt < NT; nt++) {
        int cb = nt * 8 + tg * 2;
#pragma unroll
        for (int half = 0; half < 2; half++) {
            int gr = half ? r1 : r0;
            if (gr < nRows) {
                long base = (long)gr * FO + cb;
                float v0 = acc[nt][half * 2 + 0];
                float v1 = acc[nt][half * 2 + 1];
                if (d1) { float2 dd = *(const float2*)(d1 + base); v0 += dd.x; v1 += dd.y; }
                v0 += bvs; v1 += bvs;
                if (act) {
                    v0 = (v0 >= 0.f) ? v0 : 0.2f * v0;
                    v1 = (v1 >= 0.f) ? v1 : 0.2f * v1;
                }
                if (cf) *(float2*)(cf + base) = make_float2(v0, v1);
                if (ch) *(__half2*)(ch + base) = __floats2half2_rn(v0, v1);
            }
        }
    }
}

// y = relu(a + b) : sum over K=2 stacks + inter-layer ReLU, fp32 + fp16 mirror
__global__ void k_combine(const float4* __restrict__ a, const float4* __restrict__ b,
                          float4* __restrict__ o, __half2* __restrict__ oh, int n4) {
    int i = blockIdx.x * blockDim.x + threadIdx.x;
    if (i < n4) {
        float4 x = a[i], y = b[i];
        float4 r;
        r.x = fmaxf(x.x + y.x, 0.f);
        r.y = fmaxf(x.y + y.y, 0.f);
        r.z = fmaxf(x.z + y.z, 0.f);
        r.w = fmaxf(x.w + y.w, 0.f);
        o[i] = r;
        oh[2 * i]     = __floats2half2_rn(r.x, r.y);
        oh[2 * i + 1] = __floats2half2_rn(r.z, r.w);
    }
}

// warp-per-row log_softmax, C == 32 lanes
__global__ void k_logsoftmax(const float* __restrict__ in, float* __restrict__ out, int n) {
    int warp = (blockIdx.x * blockDim.x + threadIdx.x) >> 5;
    int lane = threadIdx.x & 31;
    if (warp >= n) return;
    float v = in[(long)warp * 32 + lane];
    float m = v;
#pragma unroll
    for (int o = 16; o > 0; o >>= 1) m = fmaxf(m, __shfl_xor_sync(0xffffffffu, m, o));
    float e = expf(v - m);
    float s = e;
#pragma unroll
    for (int o = 16; o > 0; o >>= 1) s += __shfl_xor_sync(0xffffffffu, s, o);
    out[(long)warp * 32 + lane] = v - m - logf(s);
}

// ---------------- host orchestration ----------------
extern "C" void kernel_launch(void* const* d_in, const int* in_sizes, int n_in,
                              void* d_out, int out_size) {
    const float* x = (const float*)d_in[0];
    const int* ei  = (const int*)d_in[1];
    const int E = in_sizes[1] / 2;
    const int N = in_sizes[0] / 128;
    const int* row = ei;
    const int* col = ei + E;

    float *dinv, *h, *ag, *b2, *ew, *w2all;
    __half *hh, *b3h;
    int *deg, *rowptr, *bsum, *esrc;
    cudaGetSymbolAddress((void**)&dinv,   g_dinv);
    cudaGetSymbolAddress((void**)&deg,    g_deg);
    cudaGetSymbolAddress((void**)&rowptr, g_rowptr);
    cudaGetSymbolAddress((void**)&bsum,   g_bsum);
    cudaGetSymbolAddress((void**)&esrc,   g_esrc);
    cudaGetSymbolAddress((void**)&ew,     g_ew);
    cudaGetSymbolAddress((void**)&h,      g_h);
    cudaGetSymbolAddress((void**)&hh,     g_hh);
    cudaGetSymbolAddress((void**)&b3h,    g_b3h);
    cudaGetSymbolAddress((void**)&ag,     g_agg);
    cudaGetSymbolAddress((void**)&b2,     g_b2);
    cudaGetSymbolAddress((void**)&w2all,  g_w2all);

    const int nb = (N + 255) / 256;

    // gcn_norm + destination-sorted CSR build
    k_zero_int<<<nb, 256>>>(deg, N);
    k_deg<<<(E + 255) / 256, 256>>>(col, deg, E);
    k_dinv<<<nb, 256>>>(deg, dinv, N);
    k_blocksum<<<nb, 256>>>(deg, bsum, N);
    k_scanb<<<1, 256>>>(bsum, nb);
    k_scanfinal<<<nb, 256>>>(deg, bsum, rowptr, N, E);
    k_zero_int<<<nb, 256>>>(deg, N);
    k_fill<<<(E + 255) / 256, 256>>>(row, col, dinv, rowptr, deg, esrc, ew, E);

    // batched weight fold for layers 1-5 (one launch)
    float* w2p[5] = {w2all, w2all + 16384, w2all + 24576, w2all + 32768, w2all + 40960};
    {
        FoldArgs fa;
        for (int l = 0; l < 5; l++) {
            int fi = (l == 0) ? 128 : 64;
            const float* iw = (const float*)d_in[2 + l * 5 + 1];
            const float* rw = (const float*)d_in[2 + l * 5 + 2];
            const float* dw = (const float*)d_in[2 + l * 5 + 3];
            fa.iw[l]  = iw;
            fa.rw1[l] = rw + 2 * fi * 64;    // t=1 slice of [T,K,fi,64]
            fa.dw1[l] = dw + 2 * 64 * 64;    // t=1 slice of [T,K,64,64]
            fa.w2[l]  = w2p[l];
            fa.fi[l]  = fi;
        }
        k_fold_all<<<10, 256>>>(fa);
    }

    const long sK = (long)N * 64;
    const int gX  = (N + 127) / 128;

    // -------- Layer 1: Fin=128, K=2, T=2 (folded dense + commuted t1-prop) --------
    {
        const float* w  = (const float*)d_in[2];
        const float* iw = (const float*)d_in[3];
        const float* rw = (const float*)d_in[4];
        const float* bb = (const float*)d_in[6];
        dim3 gg(gX, 1, 2);
        // out0 = x@iw  (fp16 mirror only — prop source)
        k_gemm_tc<64><<<gg, 256>>>(x, 0, 128, 128, nullptr, 0, 0,
                                   iw, 128 * 64, nullptr, 0, 128,
                                   nullptr, 0, nullptr,
                                   nullptr, b3h, 0, sK, N, 0);
        // agg = prop(out0)  (2 planes)
        k_prop_h<16, 8><<<(int)((((long)N * 16) + 255) / 256), 256>>>(b3h, ag, rowptr, esrc, ew, N, sK, sK);
        // out_t0 = leaky(agg + x@rw0 + b0)  (fp16 mirror only — prop source)
        k_gemm_tc<64><<<gg, 256>>>(x, 0, 128, 128, nullptr, 0, 0,
                                   rw, 128 * 64, nullptr, 0, 128,
                                   ag, sK, bb + 0,
                                   nullptr, b3h, 0, sK, N, 1);
        // p2 = prop(out_t0)  (2 planes)
        k_prop_h<16, 8><<<(int)((((long)N * 16) + 255) / 256), 256>>>(b3h, ag, rowptr, esrc, ew, N, sK, sK);
        // final_k = leaky([p2_k|x] @ [W0_k; W2_k] + b1)   (t1 GEMM folded into B1)
        k_gemm_tc<64><<<gg, 256>>>(ag, sK, 64, 64, x, 0, 128,
                                   w, 64 * 64, w2p[0], 128 * 64, 192,
                                   nullptr, 0, bb + 1,
                                   b2, nullptr, sK, 0, N, 1);
        int n4 = (int)(sK / 4);
        k_combine<<<(n4 + 255) / 256, 256>>>((const float4*)b2, (const float4*)(b2 + sK),
                                             (float4*)h, (__half2*)hh, n4);
    }

    // -------- Layers 2-5: Fin=64, K=2, T=2 (commuted both props, folded dense+t1) --------
    for (int L = 1; L < 5; L++) {
        const float* w  = (const float*)d_in[2 + L * 5 + 0];
        const float* iw = (const float*)d_in[2 + L * 5 + 1];
        const float* rw = (const float*)d_in[2 + L * 5 + 2];
        const float* bb = (const float*)d_in[2 + L * 5 + 4];
        dim3 gg(gX, 1, 2);
        // pc = prop(h)  (single shared plane)
        k_prop_h<8, 8><<<(int)((((long)N * 8) + 255) / 256), 256>>>(hh, ag, rowptr, esrc, ew, N, 0, 0);
        // out_t0 = leaky([pc|h] @ [iw;rw0] + b0)  (fp16 mirror only — prop source)
        k_gemm_tc<64><<<gg, 256>>>(ag, 0, 64, 64, h, 0, 64,
                                   iw, 64 * 64, rw, 64 * 64, 128,
                                   nullptr, 0, bb + 0,
                                   nullptr, b3h, 0, sK, N, 1);
        // p2 = prop(out_t0)  (2 planes)
        k_prop_h<16, 8><<<(int)((((long)N * 16) + 255) / 256), 256>>>(b3h, ag, rowptr, esrc, ew, N, sK, sK);
        // final_k = leaky([p2_k|h] @ [W0_k; W2_k] + b1)
        k_gemm_tc<64><<<gg, 256>>>(ag, sK, 64, 64, h, 0, 64,
                                   w, 64 * 64, w2p[L], 64 * 64, 128,
                                   nullptr, 0, bb + 1,
                                   b2, nullptr, sK, 0, N, 1);
        int n4 = (int)(sK / 4);
        k_combine<<<(n4 + 255) / 256, 256>>>((const float4*)b2, (const float4*)(b2 + sK),
                                             (float4*)h, (__half2*)hh, n4);
    }

    // -------- Layer 6: Fin=64, FO=32, K=1, T=1 (commuted) --------
    {
        const float* iw = (const float*)d_in[2 + 5 * 5 + 1];
        const float* rw = (const float*)d_in[2 + 5 * 5 + 2];
        const float* bb = (const float*)d_in[2 + 5 * 5 + 4];
        k_prop_h<8, 8><<<(int)((((long)N * 8) + 255) / 256), 256>>>(hh, ag, rowptr, esrc, ew, N, 0, 0);
        dim3 gg(gX, 1, 1);
        k_gemm_tc<32><<<gg, 256>>>(ag, 0, 64, 64, h, 0, 64,
                                   iw, 64 * 32, rw, 64 * 32, 128,
                                   nullptr, 0, bb + 0,
                                   b2, nullptr, (long)N * 32, 0, N, 1);
        k_logsoftmax<<<(N + 7) / 8, 256>>>(b2, (float*)d_out, N);
    }
    (void)n_in; (void)out_size;
}

// round 15
// speedup vs baseline: 1.0406x; 1.0406x over previous
#include <cuda_runtime.h>
#include <cuda_fp16.h>
#include <math.h>

#define NN 50000
#define EE 800000

// ---------------- scratch (static device globals; no allocations) ----------------
__device__ float  g_dinv[NN];
__device__ int    g_deg[NN];
__device__ int    g_rowptr[NN + 1];
__device__ int    g_bsum[256];
__device__ int    g_esrc[EE];
__device__ float  g_ew[EE];
__device__ float  g_h  [(size_t)NN * 64];        // inter-layer activations (fp32)
__device__ __half g_hh [(size_t)NN * 64];        // fp16 mirror of h
__device__ __half g_b3h[(size_t)2 * NN * 64];    // fp16 out0 / out_t0 (gather source)
__device__ float  g_agg[(size_t)2 * NN * 64];    // prop destination (pc / p2)
__device__ float  g_b2 [(size_t)2 * NN * 64];    // final per-k
__device__ float  g_w2all[16384 + 4 * 8192];     // folded W2 for layers 1-5

// ---------------- setup kernels ----------------
__global__ void k_zero_int(int* p, int n) {
    int i = blockIdx.x * blockDim.x + threadIdx.x;
    if (i < n) p[i] = 0;
}
__global__ void k_deg(const int* __restrict__ col, int* __restrict__ deg, int E) {
    int e = blockIdx.x * blockDim.x + threadIdx.x;
    if (e < E) atomicAdd(&deg[col[e]], 1);
}
// block sums of deg + dinv computation (merged)
__global__ void k_blocksum(const int* __restrict__ deg, int* __restrict__ bsum,
                           float* __restrict__ dinv, int n) {
    __shared__ int s[256];
    int i = blockIdx.x * 256 + threadIdx.x;
    int d = (i < n) ? deg[i] : 0;
    if (i < n) dinv[i] = (d > 0) ? rsqrtf((float)d) : 0.f;
    s[threadIdx.x] = d;
    __syncthreads();
    for (int o = 128; o > 0; o >>= 1) {
        if (threadIdx.x < o) s[threadIdx.x] += s[threadIdx.x + o];
        __syncthreads();
    }
    if (threadIdx.x == 0) bsum[blockIdx.x] = s[0];
}
__global__ void k_scanb(int* bsum, int nb) {
    __shared__ int s[256];
    int v = (threadIdx.x < nb) ? bsum[threadIdx.x] : 0;
    s[threadIdx.x] = v;
    __syncthreads();
    for (int o = 1; o < 256; o <<= 1) {
        int t = (threadIdx.x >= o) ? s[threadIdx.x - o] : 0;
        __syncthreads();
        s[threadIdx.x] += t;
        __syncthreads();
    }
    if (threadIdx.x < nb) bsum[threadIdx.x] = s[threadIdx.x] - v;
}
// rowptr build; also zeroes deg afterward (reused as fill counter) — merged
__global__ void k_scanfinal(int* __restrict__ deg, const int* __restrict__ bsum,
                            int* __restrict__ rowptr, int n, int E) {
    __shared__ int s[256];
    int i = blockIdx.x * 256 + threadIdx.x;
    int v = (i < n) ? deg[i] : 0;
    s[threadIdx.x] = v;
    __syncthreads();
    for (int o = 1; o < 256; o <<= 1) {
        int t = (threadIdx.x >= o) ? s[threadIdx.x - o] : 0;
        __syncthreads();
        s[threadIdx.x] += t;
        __syncthreads();
    }
    if (i < n) {
        rowptr[i] = bsum[blockIdx.x] + s[threadIdx.x] - v;
        deg[i] = 0;   // reset fill counter in the same pass
    }
    if (i == 0 && blockIdx.x == 0) rowptr[n] = E;
}
__global__ void k_fill(const int* __restrict__ row, const int* __restrict__ col,
                       const float* __restrict__ dinv,
                       const int* __restrict__ rowptr, int* __restrict__ counter,
                       int* __restrict__ esrc, float* __restrict__ ew, int E) {
    int e = blockIdx.x * blockDim.x + threadIdx.x;
    if (e >= E) return;
    int r = row[e], t = col[e];
    int p = rowptr[t] + atomicAdd(&counter[t], 1);
    esrc[p] = r;
    ew[p] = dinv[r] * dinv[t];
}

// ---------------- batched weight fold: W2_k = rw1_k + 0.6*(0.5*(iw0+iw1))@dw1_k ----------------
struct FoldArgs {
    const float* iw[5];
    const float* rw1[5];
    const float* dw1[5];
    float* w2[5];
    int fi[5];
};
__global__ void k_fold_all(FoldArgs a) {
    int l = blockIdx.x >> 1, k = blockIdx.x & 1;
    int fi = a.fi[l];
    __shared__ float dws[64 * 64];
    const float* dwk = a.dw1[l] + k * 64 * 64;
    for (int i = threadIdx.x; i < 64 * 64; i += blockDim.x) dws[i] = dwk[i];
    __syncthreads();
    const float* iw = a.iw[l];
    const float* rwk = a.rw1[l] + (long)k * fi * 64;
    float* w2k = a.w2[l] + (long)k * fi * 64;
    for (int idx = threadIdx.x; idx < fi * 64; idx += blockDim.x) {
        int f = idx >> 6, q = idx & 63;
        float s = 0.f;
#pragma unroll 8
        for (int o = 0; o < 64; o++) {
            float miw = 0.5f * (iw[f * 64 + o] + iw[(long)fi * 64 + f * 64 + o]);
            s += miw * dws[o * 64 + q];
        }
        w2k[idx] = rwk[idx] + 0.6f * s;
    }
}

// ---------------- message passing: CSR gather, fp16 source ----------------
template<int CH, int F8K>
__global__ void k_prop_h(const __half* __restrict__ src, float* __restrict__ dst,
                         const int* __restrict__ rowptr, const int* __restrict__ esrc,
                         const float* __restrict__ ew, int N, long sKh, long sKf) {
    int idx = blockIdx.x * blockDim.x + threadIdx.x;
    int n = idx / CH;
    if (n >= N) return;
    int c = idx - n * CH;
    int k = c / F8K;
    int cc = c - k * F8K;
    const int F = F8K * 8;
    const __half* sb = src + (long)k * sKh + cc * 8;
    float acc[8];
#pragma unroll
    for (int q = 0; q < 8; q++) acc[q] = 0.f;
    int s0 = rowptr[n], s1 = rowptr[n + 1];
    for (int j = s0; j < s1; j++) {
        int s = esrc[j];
        float wv = ew[j];
        uint4 u = *(const uint4*)(sb + (long)s * F);
        const __half2* hp = (const __half2*)&u;
#pragma unroll
        for (int q = 0; q < 4; q++) {
            float2 f = __half22float2(hp[q]);
            acc[2 * q]     += f.x * wv;
            acc[2 * q + 1] += f.y * wv;
        }
    }
    float* db = dst + (long)k * sKf + ((long)n * F + cc * 8);
    *(float4*)db       = make_float4(acc[0], acc[1], acc[2], acc[3]);
    *(float4*)(db + 4) = make_float4(acc[4], acc[5], acc[6], acc[7]);
}

// ---------------- tf32 tensor-core helpers ----------------
__device__ __forceinline__ float to_tf32(float x) {
    unsigned u;
    asm("cvt.rna.tf32.f32 %0, %1;" : "=r"(u) : "f"(x));
    return __uint_as_float(u);
}
__device__ __forceinline__ void mma_tf32(float* c, float a0, float a1, float a2, float a3,
                                         float b0, float b1) {
    asm volatile(
        "mma.sync.aligned.m16n8k8.row.col.f32.tf32.tf32.f32 "
        "{%0,%1,%2,%3}, {%4,%5,%6,%7}, {%8,%9}, {%0,%1,%2,%3};\n"
        : "+f"(c[0]), "+f"(c[1]), "+f"(c[2]), "+f"(c[3])
        : "r"(__float_as_uint(a0)), "r"(__float_as_uint(a1)),
          "r"(__float_as_uint(a2)), "r"(__float_as_uint(a3)),
          "r"(__float_as_uint(b0)), "r"(__float_as_uint(b1)));
}

// ---------------- fused GEMM via tf32 mma.sync (per-k via blockIdx.z) ----------------
// C[k] = act( [A1|A2][k] @ [B1;B2][k] + D1[k] + bias_scalar )
template<int FO>
__global__ __launch_bounds__(256)
void k_gemm_tc(const float* __restrict__ A1, long a1K, int fin1, int lda1,
               const float* __restrict__ A2, long a2K, int lda2,
               const float* __restrict__ B1, long b1K,
               const float* __restrict__ B2, long b2K,
               int Fin,
               const float* __restrict__ D1, long dK,
               const float* __restrict__ bias,
               float* __restrict__ Cf, __half* __restrict__ Ch, long cK, long chK,
               int nRows, int act) {
    constexpr int NT = FO / 8;
    __shared__ float As[128][36];
    __shared__ float Bf[4 * NT * 32 * 2];

    const int k = blockIdx.z;
    const float* a1p = A1 + (long)k * a1K;
    const float* a2p = A2 ? (A2 + (long)k * a2K) : nullptr;
    const float* b1p = B1 + (long)k * b1K;
    const float* b2p = B2 ? (B2 + (long)k * b2K) : nullptr;
    const float* d1 = D1 ? (D1 + (long)k * dK) : nullptr;
    float* cf = Cf ? (Cf + (long)k * cK) : nullptr;
    __half* ch = Ch ? (Ch + (long)k * chK) : nullptr;

    const int tid = threadIdx.x;
    const int lane = tid & 31;
    const int warp = tid >> 5;
    const int g  = lane >> 2;
    const int tg = lane & 3;
    const int row0 = blockIdx.x * 128;
    const int wr = warp * 16;

    float acc[NT][4];
#pragma unroll
    for (int nt = 0; nt < NT; nt++)
#pragma unroll
        for (int q = 0; q < 4; q++) acc[nt][q] = 0.f;

    for (int kc = 0; kc < Fin; kc += 32) {
        __syncthreads();
        const float* Asrc; int lda, coff;
        if (kc < fin1) { Asrc = a1p; lda = lda1; coff = kc; }
        else           { Asrc = a2p; lda = lda2; coff = kc - fin1; }
        for (int i = tid; i < 128 * 8; i += 256) {
            int r = i >> 3, c4 = (i & 7) * 4;
            int gr = row0 + r;
            float4 v = make_float4(0.f, 0.f, 0.f, 0.f);
            if (gr < nRows) v = *(const float4*)(Asrc + (long)gr * lda + coff + c4);
            v.x = to_tf32(v.x); v.y = to_tf32(v.y); v.z = to_tf32(v.z); v.w = to_tf32(v.w);
            *(float4*)&As[r][c4] = v;
        }
        for (int i = tid; i < 4 * NT * 64; i += 256) {
            int r2 = i & 1;
            int lane2 = (i >> 1) & 31;
            int nt = (i >> 6) % NT;
            int ks = i / (64 * NT);
            int tg2 = lane2 & 3, g2 = lane2 >> 2;
            int kl = ks * 8 + tg2 + r2 * 4;
            int n  = nt * 8 + g2;
            int kg = kc + kl;
            float bv = (kg < fin1) ? b1p[kg * FO + n] : b2p[(kg - fin1) * FO + n];
            Bf[i] = to_tf32(bv);
        }
        __syncthreads();
#pragma unroll
        for (int ks = 0; ks < 4; ks++) {
            float a0 = As[wr + g][ks * 8 + tg];
            float a1 = As[wr + g + 8][ks * 8 + tg];
            float a2 = As[wr + g][ks * 8 + tg + 4];
            float a3 = As[wr + g + 8][ks * 8 + tg + 4];
#pragma unroll
            for (int nt = 0; nt < NT; nt++) {
                float2 b = *(const float2*)&Bf[((ks * NT + nt) * 32 + lane) * 2];
                mma_tf32(acc[nt], a0, a1, a2, a3, b.x, b.y);
            }
        }
    }

    float bvs = bias ? __ldg(bias) : 0.f;
    int r0 = row0 + wr + g;
    int r1 = r0 + 8;
#pragma unroll
    for (int nt = 0; nt < NT; nt++) {
        int cb = nt * 8 + tg * 2;
#pragma unroll
        for (int half = 0; half < 2; half++) {
            int gr = half ? r1 : r0;
            if (gr < nRows) {
                long base = (long)gr * FO + cb;
                float v0 = acc[nt][half * 2 + 0];
                float v1 = acc[nt][half * 2 + 1];
                if (d1) { float2 dd = *(const float2*)(d1 + base); v0 += dd.x; v1 += dd.y; }
                v0 += bvs; v1 += bvs;
                if (act) {
                    v0 = (v0 >= 0.f) ? v0 : 0.2f * v0;
                    v1 = (v1 >= 0.f) ? v1 : 0.2f * v1;
                }
                if (cf) *(float2*)(cf + base) = make_float2(v0, v1);
                if (ch) *(__half2*)(ch + base) = __floats2half2_rn(v0, v1);
            }
        }
    }
}

// y = relu(a + b) : sum over K=2 stacks + inter-layer ReLU, fp32 + fp16 mirror
__global__ void k_combine(const float4* __restrict__ a, const float4* __restrict__ b,
                          float4* __restrict__ o, __half2* __restrict__ oh, int n4) {
    int i = blockIdx.x * blockDim.x + threadIdx.x;
    if (i < n4) {
        float4 x = a[i], y = b[i];
        float4 r;
        r.x = fmaxf(x.x + y.x, 0.f);
        r.y = fmaxf(x.y + y.y, 0.f);
        r.z = fmaxf(x.z + y.z, 0.f);
        r.w = fmaxf(x.w + y.w, 0.f);
        o[i] = r;
        oh[2 * i]     = __floats2half2_rn(r.x, r.y);
        oh[2 * i + 1] = __floats2half2_rn(r.z, r.w);
    }
}

// warp-per-row log_softmax, C == 32 lanes
__global__ void k_logsoftmax(const float* __restrict__ in, float* __restrict__ out, int n) {
    int warp = (blockIdx.x * blockDim.x + threadIdx.x) >> 5;
    int lane = threadIdx.x & 31;
    if (warp >= n) return;
    float v = in[(long)warp * 32 + lane];
    float m = v;
#pragma unroll
    for (int o = 16; o > 0; o >>= 1) m = fmaxf(m, __shfl_xor_sync(0xffffffffu, m, o));
    float e = expf(v - m);
    float s = e;
#pragma unroll
    for (int o = 16; o > 0; o >>= 1) s += __shfl_xor_sync(0xffffffffu, s, o);
    out[(long)warp * 32 + lane] = v - m - logf(s);
}

// ---------------- host orchestration ----------------
extern "C" void kernel_launch(void* const* d_in, const int* in_sizes, int n_in,
                              void* d_out, int out_size) {
    const float* x = (const float*)d_in[0];
    const int* ei  = (const int*)d_in[1];
    const int E = in_sizes[1] / 2;
    const int N = in_sizes[0] / 128;
    const int* row = ei;
    const int* col = ei + E;

    float *dinv, *h, *ag, *b2, *ew, *w2all;
    __half *hh, *b3h;
    int *deg, *rowptr, *bsum, *esrc;
    cudaGetSymbolAddress((void**)&dinv,   g_dinv);
    cudaGetSymbolAddress((void**)&deg,    g_deg);
    cudaGetSymbolAddress((void**)&rowptr, g_rowptr);
    cudaGetSymbolAddress((void**)&bsum,   g_bsum);
    cudaGetSymbolAddress((void**)&esrc,   g_esrc);
    cudaGetSymbolAddress((void**)&ew,     g_ew);
    cudaGetSymbolAddress((void**)&h,      g_h);
    cudaGetSymbolAddress((void**)&hh,     g_hh);
    cudaGetSymbolAddress((void**)&b3h,    g_b3h);
    cudaGetSymbolAddress((void**)&ag,     g_agg);
    cudaGetSymbolAddress((void**)&b2,     g_b2);
    cudaGetSymbolAddress((void**)&w2all,  g_w2all);

    const int nb = (N + 255) / 256;

    // gcn_norm + destination-sorted CSR build (merged: dinv in blocksum, counter-zero in scanfinal)
    k_zero_int<<<nb, 256>>>(deg, N);
    k_deg<<<(E + 255) / 256, 256>>>(col, deg, E);
    k_blocksum<<<nb, 256>>>(deg, bsum, dinv, N);
    k_scanb<<<1, 256>>>(bsum, nb);
    k_scanfinal<<<nb, 256>>>(deg, bsum, rowptr, N, E);
    k_fill<<<(E + 255) / 256, 256>>>(row, col, dinv, rowptr, deg, esrc, ew, E);

    // batched weight fold for layers 1-5 (one launch)
    float* w2p[5] = {w2all, w2all + 16384, w2all + 24576, w2all + 32768, w2all + 40960};
    {
        FoldArgs fa;
        for (int l = 0; l < 5; l++) {
            int fi = (l == 0) ? 128 : 64;
            const float* iw = (const float*)d_in[2 + l * 5 + 1];
            const float* rw = (const float*)d_in[2 + l * 5 + 2];
            const float* dw = (const float*)d_in[2 + l * 5 + 3];
            fa.iw[l]  = iw;
            fa.rw1[l] = rw + 2 * fi * 64;    // t=1 slice of [T,K,fi,64]
            fa.dw1[l] = dw + 2 * 64 * 64;    // t=1 slice of [T,K,64,64]
            fa.w2[l]  = w2p[l];
            fa.fi[l]  = fi;
        }
        k_fold_all<<<10, 256>>>(fa);
    }

    const long sK = (long)N * 64;
    const int gX  = (N + 127) / 128;

    // -------- Layer 1: Fin=128, K=2, T=2 (folded dense + commuted t1-prop) --------
    {
        const float* w  = (const float*)d_in[2];
        const float* iw = (const float*)d_in[3];
        const float* rw = (const float*)d_in[4];
        const float* bb = (const float*)d_in[6];
        dim3 gg(gX, 1, 2);
        // out0 = x@iw  (fp16 mirror only — prop source)
        k_gemm_tc<64><<<gg, 256>>>(x, 0, 128, 128, nullptr, 0, 0,
                                   iw, 128 * 64, nullptr, 0, 128,
                                   nullptr, 0, nullptr,
                                   nullptr, b3h, 0, sK, N, 0);
        // agg = prop(out0)  (2 planes)
        k_prop_h<16, 8><<<(int)((((long)N * 16) + 255) / 256), 256>>>(b3h, ag, rowptr, esrc, ew, N, sK, sK);
        // out_t0 = leaky(agg + x@rw0 + b0)  (fp16 mirror only — prop source)
        k_gemm_tc<64><<<gg, 256>>>(x, 0, 128, 128, nullptr, 0, 0,
                                   rw, 128 * 64, nullptr, 0, 128,
                                   ag, sK, bb + 0,
                                   nullptr, b3h, 0, sK, N, 1);
        // p2 = prop(out_t0)  (2 planes)
        k_prop_h<16, 8><<<(int)((((long)N * 16) + 255) / 256), 256>>>(b3h, ag, rowptr, esrc, ew, N, sK, sK);
        // final_k = leaky([p2_k|x] @ [W0_k; W2_k] + b1)   (t1 GEMM folded into B1)
        k_gemm_tc<64><<<gg, 256>>>(ag, sK, 64, 64, x, 0, 128,
                                   w, 64 * 64, w2p[0], 128 * 64, 192,
                                   nullptr, 0, bb + 1,
                                   b2, nullptr, sK, 0, N, 1);
        int n4 = (int)(sK / 4);
        k_combine<<<(n4 + 255) / 256, 256>>>((const float4*)b2, (const float4*)(b2 + sK),
                                             (float4*)h, (__half2*)hh, n4);
    }

    // -------- Layers 2-5: Fin=64, K=2, T=2 (commuted both props, folded dense+t1) --------
    for (int L = 1; L < 5; L++) {
        const float* w  = (const float*)d_in[2 + L * 5 + 0];
        const float* iw = (const float*)d_in[2 + L * 5 + 1];
        const float* rw = (const float*)d_in[2 + L * 5 + 2];
        const float* bb = (const float*)d_in[2 + L * 5 + 4];
        dim3 gg(gX, 1, 2);
        // pc = prop(h)  (single shared plane)
        k_prop_h<8, 8><<<(int)((((long)N * 8) + 255) / 256), 256>>>(hh, ag, rowptr, esrc, ew, N, 0, 0);
        // out_t0 = leaky([pc|h] @ [iw;rw0] + b0)  (fp16 mirror only — prop source)
        k_gemm_tc<64><<<gg, 256>>>(ag, 0, 64, 64, h, 0, 64,
                                   iw, 64 * 64, rw, 64 * 64, 128,
                                   nullptr, 0, bb + 0,
                                   nullptr, b3h, 0, sK, N, 1);
        // p2 = prop(out_t0)  (2 planes)
        k_prop_h<16, 8><<<(int)((((long)N * 16) + 255) / 256), 256>>>(b3h, ag, rowptr, esrc, ew, N, sK, sK);
        // final_k = leaky([p2_k|h] @ [W0_k; W2_k] + b1)
        k_gemm_tc<64><<<gg, 256>>>(ag, sK, 64, 64, h, 0, 64,
                                   w, 64 * 64, w2p[L], 64 * 64, 128,
                                   nullptr, 0, bb + 1,
                                   b2, nullptr, sK, 0, N, 1);
        int n4 = (int)(sK / 4);
        k_combine<<<(n4 + 255) / 256, 256>>>((const float4*)b2, (const float4*)(b2 + sK),
                                             (float4*)h, (__half2*)hh, n4);
    }

    // -------- Layer 6: Fin=64, FO=32, K=1, T=1 (commuted) --------
    {
        const float* iw = (const float*)d_in[2 + 5 * 5 + 1];
        const float* rw = (const float*)d_in[2 + 5 * 5 + 2];
        const float* bb = (const float*)d_in[2 + 5 * 5 + 4];
        k_prop_h<8, 8><<<(int)((((long)N * 8) + 255) / 256), 256>>>(hh, ag, rowptr, esrc, ew, N, 0, 0);
        dim3 gg(gX, 1, 1);
        k_gemm_tc<32><<<gg, 256>>>(ag, 0, 64, 64, h, 0, 64,
                                   iw, 64 * 32, rw, 64 * 32, 128,
                                   nullptr, 0, bb + 0,
                                   b2, nullptr, (long)N * 32, 0, N, 1);
        k_logsoftmax<<<(N + 7) / 8, 256>>>(b2, (float*)d_out, N);
    }
    (void)n_in; (void)out_size;
}

// round 17
// speedup vs baseline: 1.0431x; 1.0024x over previous
#include <cuda_runtime.h>
#include <cuda_fp16.h>
#include <math.h>

#define NN 50000
#define EE 800000

// ---------------- scratch (static device globals; no allocations) ----------------
__device__ float  g_dinv[NN];
__device__ int    g_deg[NN];
__device__ int    g_rowptr[NN + 1];
__device__ int    g_bsum[256];
__device__ int    g_esrc[EE];
__device__ float  g_ew[EE];
__device__ float  g_h  [(size_t)NN * 64];        // inter-layer activations (fp32)
__device__ __half g_hh [(size_t)NN * 64];        // fp16 mirror of h
__device__ __half g_xh [(size_t)NN * 128];       // fp16 mirror of input x (L1 prop source)
__device__ __half g_b3h[(size_t)2 * NN * 64];    // fp16 out_t0 (gather source)
__device__ float  g_agg[(size_t)2 * NN * 64];    // prop destination (pc / p2)
__device__ float  g_b2 [(size_t)2 * NN * 64];    // final per-k
__device__ float  g_w2all[16384 + 4 * 8192];     // folded W2 for layers 1-5

// ---------------- setup kernels ----------------
__global__ void k_zero_int(int* p, int n) {
    int i = blockIdx.x * blockDim.x + threadIdx.x;
    if (i < n) p[i] = 0;
}
__global__ void k_deg(const int* __restrict__ col, int* __restrict__ deg, int E) {
    int e = blockIdx.x * blockDim.x + threadIdx.x;
    if (e < E) atomicAdd(&deg[col[e]], 1);
}
// block sums of deg + dinv computation (merged)
__global__ void k_blocksum(const int* __restrict__ deg, int* __restrict__ bsum,
                           float* __restrict__ dinv, int n) {
    __shared__ int s[256];
    int i = blockIdx.x * 256 + threadIdx.x;
    int d = (i < n) ? deg[i] : 0;
    if (i < n) dinv[i] = (d > 0) ? rsqrtf((float)d) : 0.f;
    s[threadIdx.x] = d;
    __syncthreads();
    for (int o = 128; o > 0; o >>= 1) {
        if (threadIdx.x < o) s[threadIdx.x] += s[threadIdx.x + o];
        __syncthreads();
    }
    if (threadIdx.x == 0) bsum[blockIdx.x] = s[0];
}
__global__ void k_scanb(int* bsum, int nb) {
    __shared__ int s[256];
    int v = (threadIdx.x < nb) ? bsum[threadIdx.x] : 0;
    s[threadIdx.x] = v;
    __syncthreads();
    for (int o = 1; o < 256; o <<= 1) {
        int t = (threadIdx.x >= o) ? s[threadIdx.x - o] : 0;
        __syncthreads();
        s[threadIdx.x] += t;
        __syncthreads();
    }
    if (threadIdx.x < nb) bsum[threadIdx.x] = s[threadIdx.x] - v;
}
// rowptr build; also zeroes deg afterward (reused as fill counter) — merged
__global__ void k_scanfinal(int* __restrict__ deg, const int* __restrict__ bsum,
                            int* __restrict__ rowptr, int n, int E) {
    __shared__ int s[256];
    int i = blockIdx.x * 256 + threadIdx.x;
    int v = (i < n) ? deg[i] : 0;
    s[threadIdx.x] = v;
    __syncthreads();
    for (int o = 1; o < 256; o <<= 1) {
        int t = (threadIdx.x >= o) ? s[threadIdx.x - o] : 0;
        __syncthreads();
        s[threadIdx.x] += t;
        __syncthreads();
    }
    if (i < n) {
        rowptr[i] = bsum[blockIdx.x] + s[threadIdx.x] - v;
        deg[i] = 0;   // reset fill counter in the same pass
    }
    if (i == 0 && blockIdx.x == 0) rowptr[n] = E;
}
__global__ void k_fill(const int* __restrict__ row, const int* __restrict__ col,
                       const float* __restrict__ dinv,
                       const int* __restrict__ rowptr, int* __restrict__ counter,
                       int* __restrict__ esrc, float* __restrict__ ew, int E) {
    int e = blockIdx.x * blockDim.x + threadIdx.x;
    if (e >= E) return;
    int r = row[e], t = col[e];
    int p = rowptr[t] + atomicAdd(&counter[t], 1);
    esrc[p] = r;
    ew[p] = dinv[r] * dinv[t];
}
// fp32 -> fp16 conversion (x mirror)
__global__ void k_f2h(const float2* __restrict__ in, __half2* __restrict__ out, int n2) {
    int i = blockIdx.x * blockDim.x + threadIdx.x;
    if (i < n2) {
        float2 v = in[i];
        out[i] = __floats2half2_rn(v.x, v.y);
    }
}

// ---------------- batched weight fold: W2_k = rw1_k + 0.6*(0.5*(iw0+iw1))@dw1_k ----------------
struct FoldArgs {
    const float* iw[5];
    const float* rw1[5];
    const float* dw1[5];
    float* w2[5];
    int fi[5];
};
__global__ void k_fold_all(FoldArgs a) {
    int l = blockIdx.x >> 1, k = blockIdx.x & 1;
    int fi = a.fi[l];
    __shared__ float dws[64 * 64];
    const float* dwk = a.dw1[l] + k * 64 * 64;
    for (int i = threadIdx.x; i < 64 * 64; i += blockDim.x) dws[i] = dwk[i];
    __syncthreads();
    const float* iw = a.iw[l];
    const float* rwk = a.rw1[l] + (long)k * fi * 64;
    float* w2k = a.w2[l] + (long)k * fi * 64;
    for (int idx = threadIdx.x; idx < fi * 64; idx += blockDim.x) {
        int f = idx >> 6, q = idx & 63;
        float s = 0.f;
#pragma unroll 8
        for (int o = 0; o < 64; o++) {
            float miw = 0.5f * (iw[f * 64 + o] + iw[(long)fi * 64 + f * 64 + o]);
            s += miw * dws[o * 64 + q];
        }
        w2k[idx] = rwk[idx] + 0.6f * s;
    }
}

// ---------------- message passing: CSR gather, fp16 source ----------------
template<int CH, int F8K>
__global__ void k_prop_h(const __half* __restrict__ src, float* __restrict__ dst,
                         const int* __restrict__ rowptr, const int* __restrict__ esrc,
                         const float* __restrict__ ew, int N, long sKh, long sKf) {
    int idx = blockIdx.x * blockDim.x + threadIdx.x;
    int n = idx / CH;
    if (n >= N) return;
    int c = idx - n * CH;
    int k = c / F8K;
    int cc = c - k * F8K;
    const int F = F8K * 8;
    const __half* sb = src + (long)k * sKh + cc * 8;
    float acc[8];
#pragma unroll
    for (int q = 0; q < 8; q++) acc[q] = 0.f;
    int s0 = rowptr[n], s1 = rowptr[n + 1];
    for (int j = s0; j < s1; j++) {
        int s = esrc[j];
        float wv = ew[j];
        uint4 u = *(const uint4*)(sb + (long)s * F);
        const __half2* hp = (const __half2*)&u;
#pragma unroll
        for (int q = 0; q < 4; q++) {
            float2 f = __half22float2(hp[q]);
            acc[2 * q]     += f.x * wv;
            acc[2 * q + 1] += f.y * wv;
        }
    }
    float* db = dst + (long)k * sKf + ((long)n * F + cc * 8);
    *(float4*)db       = make_float4(acc[0], acc[1], acc[2], acc[3]);
    *(float4*)(db + 4) = make_float4(acc[4], acc[5], acc[6], acc[7]);
}

// ---------------- tf32 tensor-core helpers ----------------
__device__ __forceinline__ float to_tf32(float x) {
    unsigned u;
    asm("cvt.rna.tf32.f32 %0, %1;" : "=r"(u) : "f"(x));
    return __uint_as_float(u);
}
__device__ __forceinline__ void mma_tf32(float* c, float a0, float a1, float a2, float a3,
                                         float b0, float b1) {
    asm volatile(
        "mma.sync.aligned.m16n8k8.row.col.f32.tf32.tf32.f32 "
        "{%0,%1,%2,%3}, {%4,%5,%6,%7}, {%8,%9}, {%0,%1,%2,%3};\n"
        : "+f"(c[0]), "+f"(c[1]), "+f"(c[2]), "+f"(c[3])
        : "r"(__float_as_uint(a0)), "r"(__float_as_uint(a1)),
          "r"(__float_as_uint(a2)), "r"(__float_as_uint(a3)),
          "r"(__float_as_uint(b0)), "r"(__float_as_uint(b1)));
}

// ---------------- fused GEMM via tf32 mma.sync (per-k via blockIdx.z) ----------------
// C[k] = act( [A1|A2][k] @ [B1;B2][k] + D1[k] + bias_scalar )
template<int FO>
__global__ __launch_bounds__(256)
void k_gemm_tc(const float* __restrict__ A1, long a1K, int fin1, int lda1,
               const float* __restrict__ A2, long a2K, int lda2,
               const float* __restrict__ B1, long b1K,
               const float* __restrict__ B2, long b2K,
               int Fin,
               const float* __restrict__ D1, long dK,
               const float* __restrict__ bias,
               float* __restrict__ Cf, __half* __restrict__ Ch, long cK, long chK,
               int nRows, int act) {
    constexpr int NT = FO / 8;
    __shared__ float As[128][36];
    __shared__ float Bf[4 * NT * 32 * 2];

    const int k = blockIdx.z;
    const float* a1p = A1 + (long)k * a1K;
    const float* a2p = A2 ? (A2 + (long)k * a2K) : nullptr;
    const float* b1p = B1 + (long)k * b1K;
    const float* b2p = B2 ? (B2 + (long)k * b2K) : nullptr;
    const float* d1 = D1 ? (D1 + (long)k * dK) : nullptr;
    float* cf = Cf ? (Cf + (long)k * cK) : nullptr;
    __half* ch = Ch ? (Ch + (long)k * chK) : nullptr;

    const int tid = threadIdx.x;
    const int lane = tid & 31;
    const int warp = tid >> 5;
    const int g  = lane >> 2;
    const int tg = lane & 3;
    const int row0 = blockIdx.x * 128;
    const int wr = warp * 16;

    float acc[NT][4];
#pragma unroll
    for (int nt = 0; nt < NT; nt++)
#pragma unroll
        for (int q = 0; q < 4; q++) acc[nt][q] = 0.f;

    for (int kc = 0; kc < Fin; kc += 32) {
        __syncthreads();
        const float* Asrc; int lda, coff;
        if (kc < fin1) { Asrc = a1p; lda = lda1; coff = kc; }
        else           { Asrc = a2p; lda = lda2; coff = kc - fin1; }
        for (int i = tid; i < 128 * 8; i += 256) {
            int r = i >> 3, c4 = (i & 7) * 4;
            int gr = row0 + r;
            float4 v = make_float4(0.f, 0.f, 0.f, 0.f);
            if (gr < nRows) v = *(const float4*)(Asrc + (long)gr * lda + coff + c4);
            v.x = to_tf32(v.x); v.y = to_tf32(v.y); v.z = to_tf32(v.z); v.w = to_tf32(v.w);
            *(float4*)&As[r][c4] = v;
        }
        for (int i = tid; i < 4 * NT * 64; i += 256) {
            int r2 = i & 1;
            int lane2 = (i >> 1) & 31;
            int nt = (i >> 6) % NT;
            int ks = i / (64 * NT);
            int tg2 = lane2 & 3, g2 = lane2 >> 2;
            int kl = ks * 8 + tg2 + r2 * 4;
            int n  = nt * 8 + g2;
            int kg = kc + kl;
            float bv = (kg < fin1) ? b1p[kg * FO + n] : b2p[(kg - fin1) * FO + n];
            Bf[i] = to_tf32(bv);
        }
        __syncthreads();
#pragma unroll
        for (int ks = 0; ks < 4; ks++) {
            float a0 = As[wr + g][ks * 8 + tg];
            float a1 = As[wr + g + 8][ks * 8 + tg];
            float a2 = As[wr + g][ks * 8 + tg + 4];
            float a3 = As[wr + g + 8][ks * 8 + tg + 4];
#pragma unroll
            for (int nt = 0; nt < NT; nt++) {
                float2 b = *(const float2*)&Bf[((ks * NT + nt) * 32 + lane) * 2];
                mma_tf32(acc[nt], a0, a1, a2, a3, b.x, b.y);
            }
        }
    }

    float bvs = bias ? __ldg(bias) : 0.f;
    int r0 = row0 + wr + g;
    int r1 = r0 + 8;
#pragma unroll
    for (int nt = 0; nt < NT; nt++) {
        int cb = nt * 8 + tg * 2;
#pragma unroll
        for (int half = 0; half < 2; half++) {
            int gr = half ? r1 : r0;
            if (gr < nRows) {
                long base = (long)gr * FO + cb;
                float v0 = acc[nt][half * 2 + 0];
                float v1 = acc[nt][half * 2 + 1];
                if (d1) { float2 dd = *(const float2*)(d1 + base); v0 += dd.x; v1 += dd.y; }
                v0 += bvs; v1 += bvs;
                if (act) {
                    v0 = (v0 >= 0.f) ? v0 : 0.2f * v0;
                    v1 = (v1 >= 0.f) ? v1 : 0.2f * v1;
                }
                if (cf) *(float2*)(cf + base) = make_float2(v0, v1);
                if (ch) *(__half2*)(ch + base) = __floats2half2_rn(v0, v1);
            }
        }
    }
}

// y = relu(a + b) : sum over K=2 stacks + inter-layer ReLU, fp32 + fp16 mirror
__global__ void k_combine(const float4* __restrict__ a, const float4* __restrict__ b,
                          float4* __restrict__ o, __half2* __restrict__ oh, int n4) {
    int i = blockIdx.x * blockDim.x + threadIdx.x;
    if (i < n4) {
        float4 x = a[i], y = b[i];
        float4 r;
        r.x = fmaxf(x.x + y.x, 0.f);
        r.y = fmaxf(x.y + y.y, 0.f);
        r.z = fmaxf(x.z + y.z, 0.f);
        r.w = fmaxf(x.w + y.w, 0.f);
        o[i] = r;
        oh[2 * i]     = __floats2half2_rn(r.x, r.y);
        oh[2 * i + 1] = __floats2half2_rn(r.z, r.w);
    }
}

// warp-per-row log_softmax, C == 32 lanes
__global__ void k_logsoftmax(const float* __restrict__ in, float* __restrict__ out, int n) {
    int warp = (blockIdx.x * blockDim.x + threadIdx.x) >> 5;
    int lane = threadIdx.x & 31;
    if (warp >= n) return;
    float v = in[(long)warp * 32 + lane];
    float m = v;
#pragma unroll
    for (int o = 16; o > 0; o >>= 1) m = fmaxf(m, __shfl_xor_sync(0xffffffffu, m, o));
    float e = expf(v - m);
    float s = e;
#pragma unroll
    for (int o = 16; o > 0; o >>= 1) s += __shfl_xor_sync(0xffffffffu, s, o);
    out[(long)warp * 32 + lane] = v - m - logf(s);
}

// ---------------- host orchestration ----------------
extern "C" void kernel_launch(void* const* d_in, const int* in_sizes, int n_in,
                              void* d_out, int out_size) {
    const float* x = (const float*)d_in[0];
    const int* ei  = (const int*)d_in[1];
    const int E = in_sizes[1] / 2;
    const int N = in_sizes[0] / 128;
    const int* row = ei;
    const int* col = ei + E;

    float *dinv, *h, *ag, *b2, *ew, *w2all;
    __half *hh, *xh, *b3h;
    int *deg, *rowptr, *bsum, *esrc;
    cudaGetSymbolAddress((void**)&dinv,   g_dinv);
    cudaGetSymbolAddress((void**)&deg,    g_deg);
    cudaGetSymbolAddress((void**)&rowptr, g_rowptr);
    cudaGetSymbolAddress((void**)&bsum,   g_bsum);
    cudaGetSymbolAddress((void**)&esrc,   g_esrc);
    cudaGetSymbolAddress((void**)&ew,     g_ew);
    cudaGetSymbolAddress((void**)&h,      g_h);
    cudaGetSymbolAddress((void**)&hh,     g_hh);
    cudaGetSymbolAddress((void**)&xh,     g_xh);
    cudaGetSymbolAddress((void**)&b3h,    g_b3h);
    cudaGetSymbolAddress((void**)&ag,     g_agg);
    cudaGetSymbolAddress((void**)&b2,     g_b2);
    cudaGetSymbolAddress((void**)&w2all,  g_w2all);

    const int nb = (N + 255) / 256;

    // gcn_norm + destination-sorted CSR build (merged kernels) + x fp16 mirror
    k_zero_int<<<nb, 256>>>(deg, N);
    k_deg<<<(E + 255) / 256, 256>>>(col, deg, E);
    k_blocksum<<<nb, 256>>>(deg, bsum, dinv, N);
    k_scanb<<<1, 256>>>(bsum, nb);
    k_scanfinal<<<nb, 256>>>(deg, bsum, rowptr, N, E);
    k_fill<<<(E + 255) / 256, 256>>>(row, col, dinv, rowptr, deg, esrc, ew, E);
    {
        int n2 = N * 64;   // N*128/2
        k_f2h<<<(n2 + 255) / 256, 256>>>((const float2*)x, (__half2*)xh, n2);
    }

    // batched weight fold for layers 1-5 (one launch)
    float* w2p[5] = {w2all, w2all + 16384, w2all + 24576, w2all + 32768, w2all + 40960};
    {
        FoldArgs fa;
        for (int l = 0; l < 5; l++) {
            int fi = (l == 0) ? 128 : 64;
            const float* iw = (const float*)d_in[2 + l * 5 + 1];
            const float* rw = (const float*)d_in[2 + l * 5 + 2];
            const float* dw = (const float*)d_in[2 + l * 5 + 3];
            fa.iw[l]  = iw;
            fa.rw1[l] = rw + 2 * fi * 64;    // t=1 slice of [T,K,fi,64]
            fa.dw1[l] = dw + 2 * 64 * 64;    // t=1 slice of [T,K,64,64]
            fa.w2[l]  = w2p[l];
            fa.fi[l]  = fi;
        }
        k_fold_all<<<10, 256>>>(fa);
    }

    const long sK = (long)N * 64;
    const int gX  = (N + 127) / 128;

    // -------- Layer 1: Fin=128, K=2, T=2 (both props commuted, folded dense+t1) --------
    {
        const float* w  = (const float*)d_in[2];
        const float* iw = (const float*)d_in[3];
        const float* rw = (const float*)d_in[4];
        const float* bb = (const float*)d_in[6];
        dim3 gg(gX, 1, 2);
        // pc = prop(x)  (single 128-wide plane; same bytes/edge as old 2x64 out0 gather)
        k_prop_h<16, 16><<<(int)((((long)N * 16) + 255) / 256), 256>>>(xh, ag, rowptr, esrc, ew, N, 0, 0);
        // out_t0 = leaky([pc|x] @ [iw_k; rw0_k] + b0)  (fp16 mirror only — prop source)
        k_gemm_tc<64><<<gg, 256>>>(ag, 0, 128, 128, x, 0, 128,
                                   iw, 128 * 64, rw, 128 * 64, 256,
                                   nullptr, 0, bb + 0,
                                   nullptr, b3h, 0, sK, N, 1);
        // p2 = prop(out_t0)  (2 planes)
        k_prop_h<16, 8><<<(int)((((long)N * 16) + 255) / 256), 256>>>(b3h, ag, rowptr, esrc, ew, N, sK, sK);
        // final_k = leaky([p2_k|x] @ [W0_k; W2_k] + b1)   (t1 GEMM folded into B1)
        k_gemm_tc<64><<<gg, 256>>>(ag, sK, 64, 64, x, 0, 128,
                                   w, 64 * 64, w2p[0], 128 * 64, 192,
                                   nullptr, 0, bb + 1,
                                   b2, nullptr, sK, 0, N, 1);
        int n4 = (int)(sK / 4);
        k_combine<<<(n4 + 255) / 256, 256>>>((const float4*)b2, (const float4*)(b2 + sK),
                                             (float4*)h, (__half2*)hh, n4);
    }

    // -------- Layers 2-5: Fin=64, K=2, T=2 (commuted both props, folded dense+t1) --------
    for (int L = 1; L < 5; L++) {
        const float* w  = (const float*)d_in[2 + L * 5 + 0];
        const float* iw = (const float*)d_in[2 + L * 5 + 1];
        const float* rw = (const float*)d_in[2 + L * 5 + 2];
        const float* bb = (const float*)d_in[2 + L * 5 + 4];
        dim3 gg(gX, 1, 2);
        // pc = prop(h)  (single shared plane)
        k_prop_h<8, 8><<<(int)((((long)N * 8) + 255) / 256), 256>>>(hh, ag, rowptr, esrc, ew, N, 0, 0);
        // out_t0 = leaky([pc|h] @ [iw;rw0] + b0)  (fp16 mirror only — prop source)
        k_gemm_tc<64><<<gg, 256>>>(ag, 0, 64, 64, h, 0, 64,
                                   iw, 64 * 64, rw, 64 * 64, 128,
                                   nullptr, 0, bb + 0,
                                   nullptr, b3h, 0, sK, N, 1);
        // p2 = prop(out_t0)  (2 planes)
        k_prop_h<16, 8><<<(int)((((long)N * 16) + 255) / 256), 256>>>(b3h, ag, rowptr, esrc, ew, N, sK, sK);
        // final_k = leaky([p2_k|h] @ [W0_k; W2_k] + b1)
        k_gemm_tc<64><<<gg, 256>>>(ag, sK, 64, 64, h, 0, 64,
                                   w, 64 * 64, w2p[L], 64 * 64, 128,
                                   nullptr, 0, bb + 1,
                                   b2, nullptr, sK, 0, N, 1);
        int n4 = (int)(sK / 4);
        k_combine<<<(n4 + 255) / 256, 256>>>((const float4*)b2, (const float4*)(b2 + sK),
                                             (float4*)h, (__half2*)hh, n4);
    }

    // -------- Layer 6: Fin=64, FO=32, K=1, T=1 (commuted) --------
    {
        const float* iw = (const float*)d_in[2 + 5 * 5 + 1];
        const float* rw = (const float*)d_in[2 + 5 * 5 + 2];
        const float* bb = (const float*)d_in[2 + 5 * 5 + 4];
        k_prop_h<8, 8><<<(int)((((long)N * 8) + 255) / 256), 256>>>(hh, ag, rowptr, esrc, ew, N, 0, 0);
        dim3 gg(gX, 1, 1);
        k_gemm_tc<32><<<gg, 256>>>(ag, 0, 64, 64, h, 0, 64,
                                   iw, 64 * 32, rw, 64 * 32, 128,
                                   nullptr, 0, bb + 0,
                                   b2, nullptr, (long)N * 32, 0, N, 1);
        k_logsoftmax<<<(N + 7) / 8, 256>>>(b2, (float*)d_out, N);
    }
    (void)n_in; (void)out_size;
}